// round 16
// baseline (speedup 1.0000x reference)
#include <cuda_runtime.h>
#include <cstdint>

// Problem constants
#define N_ROWS 8192
#define D_COLS 1024
#define D4     256                      // float4 columns per row
#define NBLK1  256                      // kernel1 blocks (1024 threads each)
#define ITERS  8                        // 8 quads = 32 rows per block
#define NBLK2  32                       // stage-2 blocks

// Scratch: per-block folded column sums [256][1024] floats = 1 MB
__device__ float4 g_partial[NBLK1 * D4];
// stage-2: [32][1024] floats = 128 KB
__device__ float  g_partial2[NBLK2 * D_COLS];

// Input load with 256B L2 fetch-granularity hint (dense stream, no waste)
__device__ __forceinline__ float4 ldg_256B(const float4* p) {
    float4 v;
    asm("ld.global.nc.L2::256B.v4.f32 {%0,%1,%2,%3}, [%4];"
        : "=f"(v.x), "=f"(v.y), "=f"(v.z), "=f"(v.w) : "l"(p));
    return v;
}

// ---------------------------------------------------------------------------
// Kernel 1: streaming column-sum of (source - target).
// 256 blocks x 1024 threads; static unrolled loop of 8 quad-rows (32 rows).
// Thread t's float4 column group (t%256) is fixed across iterations.
// Exit: 4-way smem fold -> 256 float4 per block (1 MB total scratch).
// ---------------------------------------------------------------------------
__global__ __launch_bounds__(1024)
void mmd_colsum_kernel(const float4* __restrict__ src,
                       const float4* __restrict__ tgt) {
    const int t   = threadIdx.x;               // 0..1023
    const int blk = blockIdx.x;                // 0..255
    const long base = (long)blk * (ITERS * 1024) + t;

    float ax = 0.f, ay = 0.f, az = 0.f, aw = 0.f;

#pragma unroll
    for (int i = 0; i < ITERS; i++) {
        const long off = base + (long)i * 1024;
        float4 s = ldg_256B(&src[off]);
        float4 v = ldg_256B(&tgt[off]);
        ax += s.x - v.x;
        ay += s.y - v.y;
        az += s.z - v.z;
        aw += s.w - v.w;
    }

    __shared__ float4 red[1024];
    float4 acc; acc.x = ax; acc.y = ay; acc.z = az; acc.w = aw;
    red[t] = acc;
    __syncthreads();
    if (t < 256) {
        float4 r1 = red[t + 256];
        float4 r2 = red[t + 512];
        float4 r3 = red[t + 768];
        acc = red[t];
        acc.x += r1.x + r2.x + r3.x;
        acc.y += r1.y + r2.y + r3.y;
        acc.z += r1.z + r2.z + r3.z;
        acc.w += r1.w + r2.w + r3.w;
        g_partial[blk * D4 + t] = acc;         // cached store: stays in L2
    }
}

// ---------------------------------------------------------------------------
// Kernel 2: reduce 256 partial rows -> 32 rows. 32 blocks x 1024 threads;
// block b sums partial rows [b*8, b*8+8) for its column. L2-hot.
// PDL: launched with programmatic serialization; prologue overlaps kernel1.
// ---------------------------------------------------------------------------
__global__ __launch_bounds__(1024)
void mmd_reduce_kernel() {
    cudaGridDependencySynchronize();           // wait for kernel1 completion
    const int d = threadIdx.x;                 // column 0..1023
    const int b = blockIdx.x;                  // 0..31
    const float* p = reinterpret_cast<const float*>(g_partial);

    float s = 0.f;
#pragma unroll
    for (int r = 0; r < 8; r++) {
        s += p[(long)(b * 8 + r) * D_COLS + d];
    }
    g_partial2[b * D_COLS + d] = s;
}

// ---------------------------------------------------------------------------
// Kernel 3: finish column sums over 32 rows (128 KB, L2-hot), square,
// reduce 1024 lanes (smem tree to 32, then warp shuffle), scale, write
// scalar. Fixed reduction order -> deterministic. PDL-gated.
// ---------------------------------------------------------------------------
__global__ __launch_bounds__(1024)
void mmd_final_kernel(float* __restrict__ out) {
    cudaGridDependencySynchronize();           // wait for kernel2 completion
    const int d = threadIdx.x;                 // column 0..1023

    float s = 0.f;
#pragma unroll
    for (int r = 0; r < 32; r++) {
        s += g_partial2[r * D_COLS + d];
    }
    float sq = s * s;

    __shared__ float red[1024];
    red[d] = sq;
    __syncthreads();
#pragma unroll
    for (int off = 512; off >= 32; off >>= 1) {
        if (d < off) red[d] += red[d + off];
        __syncthreads();
    }
    if (d < 32) {                              // final warp: shuffle reduce
        float v = red[d];
#pragma unroll
        for (int off = 16; off > 0; off >>= 1)
            v += __shfl_down_sync(0xFFFFFFFFu, v, off);
        if (d == 0)
            out[0] = v * (1.0f / ((float)N_ROWS * (float)N_ROWS));
    }
}

// ---------------------------------------------------------------------------
extern "C" void kernel_launch(void* const* d_in, const int* in_sizes, int n_in,
                              void* d_out, int out_size) {
    const float4* src = (const float4*)d_in[0];
    const float4* tgt = (const float4*)d_in[1];
    float* out = (float*)d_out;

    mmd_colsum_kernel<<<NBLK1, 1024>>>(src, tgt);

    // PDL launches: overlap launch/prologue with the predecessor kernel.
    cudaLaunchAttribute attr[1];
    attr[0].id = cudaLaunchAttributeProgrammaticStreamSerialization;
    attr[0].val.programmaticStreamSerializationAllowed = 1;

    {
        cudaLaunchConfig_t cfg = {};
        cfg.gridDim  = dim3(NBLK2, 1, 1);
        cfg.blockDim = dim3(1024, 1, 1);
        cfg.dynamicSmemBytes = 0;
        cfg.stream = 0;
        cfg.attrs = attr;
        cfg.numAttrs = 1;
        cudaLaunchKernelEx(&cfg, mmd_reduce_kernel);
    }
    {
        cudaLaunchConfig_t cfg = {};
        cfg.gridDim  = dim3(1, 1, 1);
        cfg.blockDim = dim3(1024, 1, 1);
        cfg.dynamicSmemBytes = 0;
        cfg.stream = 0;
        cfg.attrs = attr;
        cfg.numAttrs = 1;
        cudaLaunchKernelEx(&cfg, mmd_final_kernel, out);
    }
}

// round 17
// speedup vs baseline: 1.0305x; 1.0305x over previous
#include <cuda_runtime.h>
#include <cstdint>

// Problem constants
#define N_ROWS 8192
#define D_COLS 1024
#define D4     256                      // float4 columns per row
#define NBLK1  256                      // kernel1 blocks (1024 threads each)
#define ITERS  8                        // 8 quads = 32 rows per block
#define NBLK2  32                       // stage-2 blocks

// Scratch: per-block folded column sums [256][1024] floats = 1 MB
__device__ float4 g_partial[NBLK1 * D4];
// stage-2: [32][1024] floats = 128 KB
__device__ float  g_partial2[NBLK2 * D_COLS];

// Input load with 256B L2 fetch-granularity hint (dense stream, no waste)
__device__ __forceinline__ float4 ldg_256B(const float4* p) {
    float4 v;
    asm("ld.global.nc.L2::256B.v4.f32 {%0,%1,%2,%3}, [%4];"
        : "=f"(v.x), "=f"(v.y), "=f"(v.z), "=f"(v.w) : "l"(p));
    return v;
}

// ---------------------------------------------------------------------------
// Kernel 1: streaming column-sum of (source - target).
// 256 blocks x 1024 threads; static unrolled loop of 8 quad-rows (32 rows).
// Thread t's float4 column group (t%256) is fixed across iterations.
// Exit: 4-way smem fold -> 256 float4 per block (1 MB total scratch).
// ---------------------------------------------------------------------------
__global__ __launch_bounds__(1024)
void mmd_colsum_kernel(const float4* __restrict__ src,
                       const float4* __restrict__ tgt) {
    const int t   = threadIdx.x;               // 0..1023
    const int blk = blockIdx.x;                // 0..255
    const long base = (long)blk * (ITERS * 1024) + t;

    float ax = 0.f, ay = 0.f, az = 0.f, aw = 0.f;

#pragma unroll
    for (int i = 0; i < ITERS; i++) {
        const long off = base + (long)i * 1024;
        float4 s = ldg_256B(&src[off]);
        float4 v = ldg_256B(&tgt[off]);
        ax += s.x - v.x;
        ay += s.y - v.y;
        az += s.z - v.z;
        aw += s.w - v.w;
    }

    __shared__ float4 red[1024];
    float4 acc; acc.x = ax; acc.y = ay; acc.z = az; acc.w = aw;
    red[t] = acc;
    __syncthreads();
    if (t < 256) {
        float4 r1 = red[t + 256];
        float4 r2 = red[t + 512];
        float4 r3 = red[t + 768];
        acc = red[t];
        acc.x += r1.x + r2.x + r3.x;
        acc.y += r1.y + r2.y + r3.y;
        acc.z += r1.z + r2.z + r3.z;
        acc.w += r1.w + r2.w + r3.w;
        g_partial[blk * D4 + t] = acc;         // cached store: stays in L2
    }
}

// ---------------------------------------------------------------------------
// Kernel 2: reduce 256 partial rows -> 32 rows. 32 blocks x 1024 threads;
// block b sums partial rows [b*8, b*8+8) for its column. L2-hot.
// PDL: launched with programmatic serialization; prologue overlaps kernel1.
// ---------------------------------------------------------------------------
__global__ __launch_bounds__(1024)
void mmd_reduce_kernel() {
    cudaGridDependencySynchronize();           // wait for kernel1 completion
    const int d = threadIdx.x;                 // column 0..1023
    const int b = blockIdx.x;                  // 0..31
    const float* p = reinterpret_cast<const float*>(g_partial);

    float s = 0.f;
#pragma unroll
    for (int r = 0; r < 8; r++) {
        s += p[(long)(b * 8 + r) * D_COLS + d];
    }
    g_partial2[b * D_COLS + d] = s;
}

// ---------------------------------------------------------------------------
// Kernel 3: finish column sums over 32 rows (128 KB, L2-hot), square,
// block-reduce 1024 lanes, scale, write scalar. Fixed order. PDL-gated.
// ---------------------------------------------------------------------------
__global__ __launch_bounds__(1024)
void mmd_final_kernel(float* __restrict__ out) {
    cudaGridDependencySynchronize();           // wait for kernel2 completion
    const int d = threadIdx.x;                 // column 0..1023

    float s = 0.f;
#pragma unroll
    for (int r = 0; r < 32; r++) {
        s += g_partial2[r * D_COLS + d];
    }
    float sq = s * s;

    __shared__ float red[1024];
    red[d] = sq;
    __syncthreads();
#pragma unroll
    for (int off = 512; off > 0; off >>= 1) {
        if (d < off) red[d] += red[d + off];
        __syncthreads();
    }
    if (d == 0)
        out[0] = red[0] * (1.0f / ((float)N_ROWS * (float)N_ROWS));
}

// ---------------------------------------------------------------------------
extern "C" void kernel_launch(void* const* d_in, const int* in_sizes, int n_in,
                              void* d_out, int out_size) {
    const float4* src = (const float4*)d_in[0];
    const float4* tgt = (const float4*)d_in[1];
    float* out = (float*)d_out;

    mmd_colsum_kernel<<<NBLK1, 1024>>>(src, tgt);

    // PDL launches: overlap launch/prologue with the predecessor kernel.
    cudaLaunchAttribute attr[1];
    attr[0].id = cudaLaunchAttributeProgrammaticStreamSerialization;
    attr[0].val.programmaticStreamSerializationAllowed = 1;

    {
        cudaLaunchConfig_t cfg = {};
        cfg.gridDim  = dim3(NBLK2, 1, 1);
        cfg.blockDim = dim3(1024, 1, 1);
        cfg.dynamicSmemBytes = 0;
        cfg.stream = 0;
        cfg.attrs = attr;
        cfg.numAttrs = 1;
        cudaLaunchKernelEx(&cfg, mmd_reduce_kernel);
    }
    {
        cudaLaunchConfig_t cfg = {};
        cfg.gridDim  = dim3(1, 1, 1);
        cfg.blockDim = dim3(1024, 1, 1);
        cfg.dynamicSmemBytes = 0;
        cfg.stream = 0;
        cfg.attrs = attr;
        cfg.numAttrs = 1;
        cudaLaunchKernelEx(&cfg, mmd_final_kernel, out);
    }
}